// round 5
// baseline (speedup 1.0000x reference)
#include <cuda_runtime.h>
#include <math.h>

// Fused CNN + analytic quantum circuit. One CTA per TWO images, 320 threads.
// conv2 uses Blackwell packed fp32 (fma.rn.f32x2): 2 FMAs per issued instruction.
//
// Quantum part collapses analytically:
//   P_i(1) = (1 + sin f_i)/2
//   <Z_j>  = - sum_{b in {0,1}^4} prod_i P_i(b_i) * sin( sum_{i: b_i=1} w[i][j] )
//   out_j  = sigmoid(10 * <Z_j>)

typedef unsigned long long u64;

#define PACK2(d, lo, hi) \
    asm("mov.b64 %0, {%1, %2};" : "=l"(d) : "r"(__float_as_uint(lo)), "r"(__float_as_uint(hi)))
#define UNPACK2(lo, hi, s) do { unsigned _ulo, _uhi;                               \
    asm("mov.b64 {%0, %1}, %2;" : "=r"(_ulo), "=r"(_uhi) : "l"(s));                \
    lo = __uint_as_float(_ulo); hi = __uint_as_float(_uhi); } while (0)
#define FMA2(d, a, b, c) \
    asm("fma.rn.f32x2 %0, %1, %2, %3;" : "=l"(d) : "l"(a), "l"(b), "l"(c))

// dynamic shared-memory layout (floats)
#define OFF_OUT   0        // [6400] phase A: both images [2*784]; phase B: conv2 out [2][3200]
#define OFF_P1    6400     // [2][16][12][12] pooled conv1 (row = 12 floats = 48B, 16B-aligned)
#define OFF_W2    11008    // [4608] conv2 weights, native HWIO [k][ci][co]
#define OFF_P2    11008    // alias over W2 (dead after conv2): [2][800]
#define OFF_W1    15616    // [144]
#define OFF_B1    15760    // [16]
#define OFF_B2    15776    // [32]
#define OFF_FEAT  15808    // [8]
#define SM_FLOATS 15816
#define SM_BYTES  (SM_FLOATS * 4)

__global__ __launch_bounds__(320, 2)
void hybrid_kernel(const float* __restrict__ x,
                   const float* __restrict__ w1g, const float* __restrict__ b1g,
                   const float* __restrict__ w2g, const float* __restrict__ b2g,
                   const float* __restrict__ dwg, const float* __restrict__ dbg,
                   const float* __restrict__ qwg,
                   float* __restrict__ out, int B)
{
    extern __shared__ __align__(16) float sm[];
    float* s_out  = sm + OFF_OUT;
    float* s_p1   = sm + OFF_P1;
    float* s_w2   = sm + OFF_W2;
    float* s_p2   = sm + OFF_P2;
    float* s_w1   = sm + OFF_W1;
    float* s_b1   = sm + OFF_B1;
    float* s_b2   = sm + OFF_B2;
    float* s_feat = sm + OFF_FEAT;

    const int tid  = threadIdx.x;
    const int img0 = blockIdx.x * 2;
    const bool has2 = (img0 + 1) < B;
    const int nimg = has2 ? 2 : 1;

    // ---------------- load phase ----------------
    {
        const float* xin = x + img0 * 784;
        const int cnt = nimg * 784;
        for (int i = tid; i < cnt; i += 320) s_out[i] = xin[i];
    }
    {
        const float4* src = (const float4*)w2g;
        float4* dst = (float4*)s_w2;
        for (int i = tid; i < 1152; i += 320) dst[i] = src[i];
    }
    for (int i = tid; i < 144; i += 320) s_w1[i] = w1g[i];
    if (tid < 16) s_b1[tid] = b1g[tid];
    if (tid < 32) s_b2[tid] = b2g[tid];
    if (tid < 8)  s_feat[tid] = dbg[tid & 3];
    __syncthreads();

    // ---------------- conv1 (3x3x1x16) + relu + 2x2 maxpool -> s_p1[2][16][12][12] --
    // 768 half-row units: (im, co, py, half of 6 px). Critical path = 3 halves.
    for (int u = tid; u < 768; u += 320) {
        const int half = u & 1;
        const int ppy  = (u >> 1) % 12;
        const int co   = ((u >> 1) / 12) & 15;
        const int im   = u >> 9;                 // u/512? no: 768/2=384 per im
        const int im2  = u / 384;
        (void)im;
        float w[9];
        #pragma unroll
        for (int k = 0; k < 9; k++) w[k] = s_w1[k * 16 + co];
        const float bias = s_b1[co];
        const float* in0 = s_out + im2 * 784 + (2 * ppy) * 28;
        float* p1row = s_p1 + im2 * 2304 + (co * 12 + ppy) * 12;
        const int px0 = half * 6;

        float win[4][4];
        #pragma unroll
        for (int r = 0; r < 4; r++) {
            win[r][2] = in0[r * 28 + 2 * px0 + 0];
            win[r][3] = in0[r * 28 + 2 * px0 + 1];
        }
        #pragma unroll
        for (int dpx = 0; dpx < 6; dpx++) {
            const int px = px0 + dpx;
            #pragma unroll
            for (int r = 0; r < 4; r++) {
                win[r][0] = win[r][2];
                win[r][1] = win[r][3];
                win[r][2] = in0[r * 28 + 2 * px + 2];
                win[r][3] = in0[r * 28 + 2 * px + 3];
            }
            float best = -1e30f;
            #pragma unroll
            for (int dy = 0; dy < 2; dy++) {
                #pragma unroll
                for (int dx = 0; dx < 2; dx++) {
                    float acc = bias;
                    #pragma unroll
                    for (int ky = 0; ky < 3; ky++) {
                        #pragma unroll
                        for (int kx = 0; kx < 3; kx++)
                            acc += win[dy + ky][dx + kx] * w[ky * 3 + kx];
                    }
                    best = fmaxf(best, acc);
                }
            }
            p1row[px] = fmaxf(best, 0.0f);
        }
    }
    __syncthreads();

    // ---------------- conv2 (3x3x16x32) + relu, 2 images, packed f32x2 -------------
    // unit = (co 0..31, row oy 0..9). 5 paired accumulators per image.
    {
        const int co = tid & 31;
        const int oy = tid >> 5;
        const float bias = s_b2[co];
        u64 bias2; PACK2(bias2, bias, bias);
        u64 accA[5], accB[5];
        #pragma unroll
        for (int k = 0; k < 5; k++) { accA[k] = bias2; accB[k] = bias2; }

        #pragma unroll 1
        for (int ci = 0; ci < 16; ci++) {
            // 9 weights (HWIO, lanes=co consecutive -> conflict-free), packed (w,w)
            const float* wbase = s_w2 + ci * 32 + co;
            u64 ww[9];
            #pragma unroll
            for (int t = 0; t < 9; t++) {
                const float wv = wbase[t * 512];
                PACK2(ww[t], wv, wv);
            }
            const int rbase0 = (ci * 12 + oy) * 12;

            #pragma unroll
            for (int ky = 0; ky < 3; ky++) {
                const int rbase = rbase0 + ky * 12;
                #pragma unroll
                for (int im = 0; im < 2; im++) {
                    const float4* rp = (const float4*)(s_p1 + im * 2304 + rbase);
                    const float4 A = rp[0], Bv = rp[1], C = rp[2];
                    u64 p0, p1, p2, p3, p4, p5, q0, q1, q2, q3, q4;
                    PACK2(p0, A.x, A.y);  PACK2(p1, A.z, A.w);
                    PACK2(p2, Bv.x, Bv.y); PACK2(p3, Bv.z, Bv.w);
                    PACK2(p4, C.x, C.y);  PACK2(p5, C.z, C.w);
                    PACK2(q0, A.y, A.z);  PACK2(q1, A.w, Bv.x);
                    PACK2(q2, Bv.y, Bv.z); PACK2(q3, Bv.w, C.x);
                    PACK2(q4, C.y, C.z);
                    const u64 t0 = ww[ky * 3 + 0];
                    const u64 t1 = ww[ky * 3 + 1];
                    const u64 t2 = ww[ky * 3 + 2];
                    u64* acc = im ? accB : accA;
                    FMA2(acc[0], p0, t0, acc[0]); FMA2(acc[0], q0, t1, acc[0]); FMA2(acc[0], p1, t2, acc[0]);
                    FMA2(acc[1], p1, t0, acc[1]); FMA2(acc[1], q1, t1, acc[1]); FMA2(acc[1], p2, t2, acc[1]);
                    FMA2(acc[2], p2, t0, acc[2]); FMA2(acc[2], q2, t1, acc[2]); FMA2(acc[2], p3, t2, acc[2]);
                    FMA2(acc[3], p3, t0, acc[3]); FMA2(acc[3], q3, t1, acc[3]); FMA2(acc[3], p4, t2, acc[3]);
                    FMA2(acc[4], p4, t0, acc[4]); FMA2(acc[4], q4, t1, acc[4]); FMA2(acc[4], p5, t2, acc[4]);
                }
            }
        }
        #pragma unroll
        for (int k = 0; k < 5; k++) {
            float lo, hi;
            UNPACK2(lo, hi, accA[k]);
            s_out[(oy * 10 + 2 * k    ) * 32 + co] = fmaxf(lo, 0.0f);
            s_out[(oy * 10 + 2 * k + 1) * 32 + co] = fmaxf(hi, 0.0f);
            UNPACK2(lo, hi, accB[k]);
            s_out[3200 + (oy * 10 + 2 * k    ) * 32 + co] = fmaxf(lo, 0.0f);
            s_out[3200 + (oy * 10 + 2 * k + 1) * 32 + co] = fmaxf(hi, 0.0f);
        }
    }
    __syncthreads();   // also retires all s_w2 reads before s_p2 aliases it

    // ---------------- 2x2 maxpool -> s_p2[2][800] (NHWC flatten) -------------------
    for (int o = tid; o < 1600; o += 320) {
        const int im  = o >= 800;
        const int oo  = o - im * 800;
        const int co  = oo & 31;
        const int pos = oo >> 5;
        const int r   = pos / 5;
        const int cl  = pos - r * 5;
        const float* base = s_out + im * 3200;
        const float v0 = base[((2 * r    ) * 10 + 2 * cl    ) * 32 + co];
        const float v1 = base[((2 * r    ) * 10 + 2 * cl + 1) * 32 + co];
        const float v2 = base[((2 * r + 1) * 10 + 2 * cl    ) * 32 + co];
        const float v3 = base[((2 * r + 1) * 10 + 2 * cl + 1) * 32 + co];
        s_p2[o] = fmaxf(fmaxf(v0, v1), fmaxf(v2, v3));
    }
    __syncthreads();

    // ---------------- dense 800 -> 4, both images ----------------------------------
    {
        float pA0 = 0.f, pA1 = 0.f, pA2 = 0.f, pA3 = 0.f;
        float pB0 = 0.f, pB1 = 0.f, pB2 = 0.f, pB3 = 0.f;
        for (int k = tid; k < 800; k += 320) {
            const float vA = s_p2[k];
            const float vB = s_p2[800 + k];
            const float4 w = *(const float4*)(dwg + k * 4);
            pA0 += vA * w.x; pA1 += vA * w.y; pA2 += vA * w.z; pA3 += vA * w.w;
            pB0 += vB * w.x; pB1 += vB * w.y; pB2 += vB * w.z; pB3 += vB * w.w;
        }
        #pragma unroll
        for (int off = 16; off; off >>= 1) {
            pA0 += __shfl_down_sync(0xffffffffu, pA0, off);
            pA1 += __shfl_down_sync(0xffffffffu, pA1, off);
            pA2 += __shfl_down_sync(0xffffffffu, pA2, off);
            pA3 += __shfl_down_sync(0xffffffffu, pA3, off);
            pB0 += __shfl_down_sync(0xffffffffu, pB0, off);
            pB1 += __shfl_down_sync(0xffffffffu, pB1, off);
            pB2 += __shfl_down_sync(0xffffffffu, pB2, off);
            pB3 += __shfl_down_sync(0xffffffffu, pB3, off);
        }
        if ((tid & 31) == 0) {
            atomicAdd(&s_feat[0], pA0);
            atomicAdd(&s_feat[1], pA1);
            atomicAdd(&s_feat[2], pA2);
            atomicAdd(&s_feat[3], pA3);
            atomicAdd(&s_feat[4], pB0);
            atomicAdd(&s_feat[5], pB1);
            atomicAdd(&s_feat[6], pB2);
            atomicAdd(&s_feat[7], pB3);
        }
    }
    __syncthreads();

    // ---------------- analytic quantum circuit + sigmoid ---------------------------
    if (tid < 8) {
        const int im = tid >> 2;
        const int j  = tid & 3;
        if (im == 0 || has2) {
            float pr1[4];
            #pragma unroll
            for (int i = 0; i < 4; i++) {
                const float f = tanhf(s_feat[im * 4 + i]);
                pr1[i] = 0.5f * (1.0f + sinf(f));
            }
            float wj[4];
            #pragma unroll
            for (int i = 0; i < 4; i++) wj[i] = qwg[i * 4 + j];

            float q = 0.0f;
            #pragma unroll
            for (int b = 0; b < 16; b++) {
                float prob = 1.0f, ang = 0.0f;
                #pragma unroll
                for (int i = 0; i < 4; i++) {
                    if (b & (1 << i)) { prob *= pr1[i];        ang += wj[i]; }
                    else              { prob *= 1.0f - pr1[i]; }
                }
                q -= prob * sinf(ang);
            }
            out[(img0 + im) * 4 + j] = 1.0f / (1.0f + expf(-10.0f * q));
        }
    }
}

extern "C" void kernel_launch(void* const* d_in, const int* in_sizes, int n_in,
                              void* d_out, int out_size)
{
    const float* x   = (const float*)d_in[0];
    const float* w1  = (const float*)d_in[1];
    const float* b1  = (const float*)d_in[2];
    const float* w2  = (const float*)d_in[3];
    const float* b2  = (const float*)d_in[4];
    const float* dw  = (const float*)d_in[5];
    const float* db  = (const float*)d_in[6];
    const float* qw  = (const float*)d_in[7];
    float* out = (float*)d_out;

    const int B = in_sizes[0] / 784;   // NHWC 28*28*1
    static bool attr_set = false;
    if (!attr_set) {
        cudaFuncSetAttribute(hybrid_kernel,
                             cudaFuncAttributeMaxDynamicSharedMemorySize, SM_BYTES);
        attr_set = true;
    }
    hybrid_kernel<<<(B + 1) / 2, 320, SM_BYTES>>>(x, w1, b1, w2, b2, dw, db, qw, out, B);
}

// round 6
// speedup vs baseline: 1.3003x; 1.3003x over previous
#include <cuda_runtime.h>
#include <math.h>

// Fused CNN + analytic quantum circuit. One CTA per TWO images, 320 threads,
// 3 CTAs/SM. Weights in smem kept in native HWIO order (conflict-free coalesced
// LDS); each weight load amortized over 2 images' worth of FMAs.
//
// Quantum part collapses analytically:
//   P_i(1) = (1 + sin f_i)/2
//   <Z_j>  = - sum_{b in {0,1}^4} prod_i P_i(b_i) * sin( sum_{i: b_i=1} w[i][j] )
//   out_j  = sigmoid(10 * <Z_j>)

// dynamic shared-memory layout (floats)
#define OFF_OUT   0        // [6400] phase A: both images [2*784]; phase B: conv2 out [2][3200]
#define OFF_P1    6400     // [2][16][12][12] pooled conv1 (row = 12 floats = 48B, 16B-aligned)
#define OFF_W2    11008    // [4608] conv2 weights, native HWIO [k][ci][co]
#define OFF_P2    11008    // alias over W2 (dead after conv2): [2][800]
#define OFF_W1    15616    // [144]
#define OFF_B1    15760    // [16]
#define OFF_B2    15776    // [32]
#define OFF_FEAT  15808    // [8]  (dense out + bias, 2 images x 4)
#define SM_FLOATS 15816
#define SM_BYTES  (SM_FLOATS * 4)

__global__ __launch_bounds__(320, 3)
void hybrid_kernel(const float* __restrict__ x,
                   const float* __restrict__ w1g, const float* __restrict__ b1g,
                   const float* __restrict__ w2g, const float* __restrict__ b2g,
                   const float* __restrict__ dwg, const float* __restrict__ dbg,
                   const float* __restrict__ qwg,
                   float* __restrict__ out, int B)
{
    extern __shared__ __align__(16) float sm[];
    float* s_out  = sm + OFF_OUT;
    float* s_p1   = sm + OFF_P1;
    float* s_w2   = sm + OFF_W2;
    float* s_p2   = sm + OFF_P2;
    float* s_w1   = sm + OFF_W1;
    float* s_b1   = sm + OFF_B1;
    float* s_b2   = sm + OFF_B2;
    float* s_feat = sm + OFF_FEAT;

    const int tid  = threadIdx.x;
    const int img0 = blockIdx.x * 2;
    const bool has2 = (img0 + 1) < B;
    const int nimg = has2 ? 2 : 1;

    // ---------------- load phase ----------------
    // two consecutive images are contiguous in x: one coalesced copy
    {
        const float* xin = x + img0 * 784;
        const int cnt = nimg * 784;
        for (int i = tid; i < cnt; i += 320) s_out[i] = xin[i];
    }
    // conv2 weights: straight coalesced float4 copy (4608 floats)
    {
        const float4* src = (const float4*)w2g;
        float4* dst = (float4*)s_w2;
        for (int i = tid; i < 1152; i += 320) dst[i] = src[i];
    }
    for (int i = tid; i < 144; i += 320) s_w1[i] = w1g[i];
    if (tid < 16) s_b1[tid] = b1g[tid];
    if (tid < 32) s_b2[tid] = b2g[tid];
    if (tid < 8)  s_feat[tid] = dbg[tid & 3];
    __syncthreads();

    // ---------------- conv1 (3x3x1x16) + relu + 2x2 maxpool -> s_p1[2][16][12][12] --
    // Only pooled rows/cols 0..11 feed conv2's useful region. 192 units, loop images.
    if (tid < 192) {
        const int co = tid & 15;
        const int py = tid >> 4;               // 0..11
        float w[9];
        #pragma unroll
        for (int k = 0; k < 9; k++) w[k] = s_w1[k * 16 + co];
        const float bias = s_b1[co];

        #pragma unroll 1
        for (int im = 0; im < 2; im++) {
            const float* in0 = s_out + im * 784 + (2 * py) * 28;
            float* p1row = s_p1 + im * 2304 + (co * 12 + py) * 12;

            float win[4][4];
            #pragma unroll
            for (int r = 0; r < 4; r++) {
                win[r][2] = in0[r * 28 + 0];
                win[r][3] = in0[r * 28 + 1];
            }
            #pragma unroll 1
            for (int px = 0; px < 12; px++) {
                #pragma unroll
                for (int r = 0; r < 4; r++) {
                    win[r][0] = win[r][2];
                    win[r][1] = win[r][3];
                    win[r][2] = in0[r * 28 + 2 * px + 2];
                    win[r][3] = in0[r * 28 + 2 * px + 3];
                }
                float best = -1e30f;
                #pragma unroll
                for (int dy = 0; dy < 2; dy++) {
                    #pragma unroll
                    for (int dx = 0; dx < 2; dx++) {
                        float acc = bias;
                        #pragma unroll
                        for (int ky = 0; ky < 3; ky++) {
                            #pragma unroll
                            for (int kx = 0; kx < 3; kx++)
                                acc += win[dy + ky][dx + kx] * w[ky * 3 + kx];
                        }
                        best = fmaxf(best, acc);
                    }
                }
                p1row[px] = fmaxf(best, 0.0f);
            }
        }
    }
    __syncthreads();

    // ---------------- conv2 (3x3x16x32) + relu, 2 images -> s_out [im][oy][ox][co] --
    // unit = (co 0..31, row oy 0..9): 320 units; each does 2 images (20 accumulators).
    {
        const int co = tid & 31;
        const int oy = tid >> 5;
        const float bias = s_b2[co];
        float accA[10], accB[10];
        #pragma unroll
        for (int i = 0; i < 10; i++) { accA[i] = bias; accB[i] = bias; }

        #pragma unroll 1
        for (int ci = 0; ci < 16; ci++) {
            #pragma unroll
            for (int ky = 0; ky < 3; ky++) {
                // weights: lanes = co -> consecutive addresses, conflict-free (1 wf each)
                const float* wrow = s_w2 + (ky * 3) * 512 + ci * 32 + co;
                const float w0 = wrow[0];
                const float w1 = wrow[512];
                const float w2 = wrow[1024];
                const int rbase = (ci * 12 + oy + ky) * 12;

                {   // image A: 12-float row via 3 broadcast LDS.128
                    const float4* rp = (const float4*)(s_p1 + rbase);
                    const float4 A = rp[0], Bv = rp[1], C = rp[2];
                    const float a[12] = {A.x, A.y, A.z, A.w, Bv.x, Bv.y, Bv.z, Bv.w,
                                         C.x, C.y, C.z, C.w};
                    #pragma unroll
                    for (int ox = 0; ox < 10; ox++) {
                        accA[ox] += a[ox] * w0;
                        accA[ox] += a[ox + 1] * w1;
                        accA[ox] += a[ox + 2] * w2;
                    }
                }
                {   // image B
                    const float4* rp = (const float4*)(s_p1 + 2304 + rbase);
                    const float4 A = rp[0], Bv = rp[1], C = rp[2];
                    const float a[12] = {A.x, A.y, A.z, A.w, Bv.x, Bv.y, Bv.z, Bv.w,
                                         C.x, C.y, C.z, C.w};
                    #pragma unroll
                    for (int ox = 0; ox < 10; ox++) {
                        accB[ox] += a[ox] * w0;
                        accB[ox] += a[ox + 1] * w1;
                        accB[ox] += a[ox + 2] * w2;
                    }
                }
            }
        }
        #pragma unroll
        for (int ox = 0; ox < 10; ox++) {
            s_out[(oy * 10 + ox) * 32 + co]        = fmaxf(accA[ox], 0.0f);
            s_out[3200 + (oy * 10 + ox) * 32 + co] = fmaxf(accB[ox], 0.0f);
        }
    }
    __syncthreads();   // also retires all s_w2 reads before s_p2 aliases it

    // ---------------- 2x2 maxpool -> s_p2[2][800] (NHWC flatten) -------------------
    for (int o = tid; o < 1600; o += 320) {
        const int im  = o >= 800;
        const int oo  = o - im * 800;
        const int co  = oo & 31;
        const int pos = oo >> 5;
        const int r   = pos / 5;
        const int cl  = pos - r * 5;
        const float* base = s_out + im * 3200;
        const float v0 = base[((2 * r    ) * 10 + 2 * cl    ) * 32 + co];
        const float v1 = base[((2 * r    ) * 10 + 2 * cl + 1) * 32 + co];
        const float v2 = base[((2 * r + 1) * 10 + 2 * cl    ) * 32 + co];
        const float v3 = base[((2 * r + 1) * 10 + 2 * cl + 1) * 32 + co];
        s_p2[o] = fmaxf(fmaxf(v0, v1), fmaxf(v2, v3));
    }
    __syncthreads();

    // ---------------- dense 800 -> 4, both images (one weight load serves both) ----
    {
        float pA0 = 0.f, pA1 = 0.f, pA2 = 0.f, pA3 = 0.f;
        float pB0 = 0.f, pB1 = 0.f, pB2 = 0.f, pB3 = 0.f;
        for (int k = tid; k < 800; k += 320) {
            const float vA = s_p2[k];
            const float vB = s_p2[800 + k];
            const float4 w = *(const float4*)(dwg + k * 4);
            pA0 += vA * w.x; pA1 += vA * w.y; pA2 += vA * w.z; pA3 += vA * w.w;
            pB0 += vB * w.x; pB1 += vB * w.y; pB2 += vB * w.z; pB3 += vB * w.w;
        }
        #pragma unroll
        for (int off = 16; off; off >>= 1) {
            pA0 += __shfl_down_sync(0xffffffffu, pA0, off);
            pA1 += __shfl_down_sync(0xffffffffu, pA1, off);
            pA2 += __shfl_down_sync(0xffffffffu, pA2, off);
            pA3 += __shfl_down_sync(0xffffffffu, pA3, off);
            pB0 += __shfl_down_sync(0xffffffffu, pB0, off);
            pB1 += __shfl_down_sync(0xffffffffu, pB1, off);
            pB2 += __shfl_down_sync(0xffffffffu, pB2, off);
            pB3 += __shfl_down_sync(0xffffffffu, pB3, off);
        }
        if ((tid & 31) == 0) {
            atomicAdd(&s_feat[0], pA0);
            atomicAdd(&s_feat[1], pA1);
            atomicAdd(&s_feat[2], pA2);
            atomicAdd(&s_feat[3], pA3);
            atomicAdd(&s_feat[4], pB0);
            atomicAdd(&s_feat[5], pB1);
            atomicAdd(&s_feat[6], pB2);
            atomicAdd(&s_feat[7], pB3);
        }
    }
    __syncthreads();

    // ---------------- analytic quantum circuit + sigmoid ---------------------------
    if (tid < 8) {
        const int im = tid >> 2;
        const int j  = tid & 3;
        if (im == 0 || has2) {
            float pr1[4];
            #pragma unroll
            for (int i = 0; i < 4; i++) {
                const float f = tanhf(s_feat[im * 4 + i]);
                pr1[i] = 0.5f * (1.0f + sinf(f));
            }
            float wj[4];
            #pragma unroll
            for (int i = 0; i < 4; i++) wj[i] = qwg[i * 4 + j];

            float q = 0.0f;
            #pragma unroll
            for (int b = 0; b < 16; b++) {
                float prob = 1.0f, ang = 0.0f;
                #pragma unroll
                for (int i = 0; i < 4; i++) {
                    if (b & (1 << i)) { prob *= pr1[i];        ang += wj[i]; }
                    else              { prob *= 1.0f - pr1[i]; }
                }
                q -= prob * sinf(ang);
            }
            out[(img0 + im) * 4 + j] = 1.0f / (1.0f + expf(-10.0f * q));
        }
    }
}

extern "C" void kernel_launch(void* const* d_in, const int* in_sizes, int n_in,
                              void* d_out, int out_size)
{
    const float* x   = (const float*)d_in[0];
    const float* w1  = (const float*)d_in[1];
    const float* b1  = (const float*)d_in[2];
    const float* w2  = (const float*)d_in[3];
    const float* b2  = (const float*)d_in[4];
    const float* dw  = (const float*)d_in[5];
    const float* db  = (const float*)d_in[6];
    const float* qw  = (const float*)d_in[7];
    float* out = (float*)d_out;

    const int B = in_sizes[0] / 784;   // NHWC 28*28*1
    static bool attr_set = false;
    if (!attr_set) {
        cudaFuncSetAttribute(hybrid_kernel,
                             cudaFuncAttributeMaxDynamicSharedMemorySize, SM_BYTES);
        attr_set = true;
    }
    hybrid_kernel<<<(B + 1) / 2, 320, SM_BYTES>>>(x, w1, b1, w2, b2, dw, db, qw, out, B);
}

// round 8
// speedup vs baseline: 1.3723x; 1.0554x over previous
#include <cuda_runtime.h>
#include <math.h>

// Fused CNN + analytic quantum circuit. One CTA per TWO images, 320 threads,
// 3 CTAs/SM. conv2 computes row-PAIRS and fuses the 2x2 maxpool in registers,
// eliminating the pool phase and its smem round trip.
//
// Quantum part collapses analytically:
//   P_i(1) = (1 + sin f_i)/2
//   <Z_j>  = - sum_{b in {0,1}^4} prod_i P_i(b_i) * sin( sum_{i: b_i=1} w[i][j] )
//   out_j  = sigmoid(10 * <Z_j>)

// dynamic shared-memory layout (floats)
#define OFF_OUT   0        // [1600] phase A: both images [2*784]; phase B: s_p2 [2][800]
#define OFF_P1    1600     // [2][16][12][12] pooled conv1 (row = 12 floats = 48B, 16B-aligned)
#define OFF_W2    6208     // [4608] conv2 weights, native HWIO [k][ci][co]
#define OFF_W1    10816    // [144]
#define OFF_B1    10960    // [16]
#define OFF_B2    10976    // [32]
#define OFF_FEAT  11008    // [8]  (dense out + bias, 2 images x 4)
#define SM_FLOATS 11016
#define SM_BYTES  (SM_FLOATS * 4)

__global__ __launch_bounds__(320, 3)
void hybrid_kernel(const float* __restrict__ x,
                   const float* __restrict__ w1g, const float* __restrict__ b1g,
                   const float* __restrict__ w2g, const float* __restrict__ b2g,
                   const float* __restrict__ dwg, const float* __restrict__ dbg,
                   const float* __restrict__ qwg,
                   float* __restrict__ out, int B)
{
    extern __shared__ __align__(16) float sm[];
    float* s_img  = sm + OFF_OUT;     // phase A
    float* s_p2   = sm + OFF_OUT;     // phase B (images dead after conv1)
    float* s_p1   = sm + OFF_P1;
    float* s_w2   = sm + OFF_W2;
    float* s_w1   = sm + OFF_W1;
    float* s_b1   = sm + OFF_B1;
    float* s_b2   = sm + OFF_B2;
    float* s_feat = sm + OFF_FEAT;

    const int tid  = threadIdx.x;
    const int img0 = blockIdx.x * 2;
    const bool has2 = (img0 + 1) < B;
    const int nimg = has2 ? 2 : 1;

    // ---------------- load phase ----------------
    {
        const float* xin = x + img0 * 784;
        const int cnt = nimg * 784;
        for (int i = tid; i < cnt; i += 320) s_img[i] = xin[i];
    }
    {
        const float4* src = (const float4*)w2g;
        float4* dst = (float4*)s_w2;
        for (int i = tid; i < 1152; i += 320) dst[i] = src[i];
    }
    for (int i = tid; i < 144; i += 320) s_w1[i] = w1g[i];
    if (tid < 16) s_b1[tid] = b1g[tid];
    if (tid < 32) s_b2[tid] = b2g[tid];
    if (tid < 8)  s_feat[tid] = dbg[tid & 3];
    __syncthreads();

    // ---------------- conv1 (3x3x1x16) + relu + 2x2 maxpool -> s_p1[2][16][12][12] --
    // 768 half-row units (im, co, py, half): all 320 threads busy, crit path 1.5 rows.
    for (int u = tid; u < 768; u += 320) {
        const int im   = u / 384;
        const int rem  = u - im * 384;
        const int half = rem & 1;
        const int idx  = rem >> 1;          // 0..191
        const int co   = idx & 15;
        const int py   = idx >> 4;          // 0..11
        float w[9];
        #pragma unroll
        for (int k = 0; k < 9; k++) w[k] = s_w1[k * 16 + co];
        const float bias = s_b1[co];
        const float* in0 = s_img + im * 784 + (2 * py) * 28;
        float* p1row = s_p1 + im * 2304 + (co * 12 + py) * 12;
        const int px0 = half * 6;

        float win[4][4];
        #pragma unroll
        for (int r = 0; r < 4; r++) {
            const float2 v = *(const float2*)(in0 + r * 28 + 2 * px0);
            win[r][2] = v.x; win[r][3] = v.y;
        }
        #pragma unroll
        for (int dpx = 0; dpx < 6; dpx++) {
            const int px = px0 + dpx;
            #pragma unroll
            for (int r = 0; r < 4; r++) {
                win[r][0] = win[r][2];
                win[r][1] = win[r][3];
                const float2 v = *(const float2*)(in0 + r * 28 + 2 * px + 2);
                win[r][2] = v.x; win[r][3] = v.y;
            }
            float best = -1e30f;
            #pragma unroll
            for (int dy = 0; dy < 2; dy++) {
                #pragma unroll
                for (int dx = 0; dx < 2; dx++) {
                    float acc = bias;
                    #pragma unroll
                    for (int ky = 0; ky < 3; ky++) {
                        #pragma unroll
                        for (int kx = 0; kx < 3; kx++)
                            acc += win[dy + ky][dx + kx] * w[ky * 3 + kx];
                    }
                    best = fmaxf(best, acc);
                }
            }
            p1row[px] = fmaxf(best, 0.0f);
        }
    }
    __syncthreads();

    // ---------------- conv2 (3x3x16x32) + relu + FUSED 2x2 maxpool -> s_p2 ---------
    // thread = (im, co, oy-pair): 2 x 32 x 5 = 320 units.
    // Computes output rows 2*oyp and 2*oyp+1, pools in registers, writes 5 floats.
    {
        const int im  = tid >= 160;
        const int t   = tid - im * 160;    // 0..159  (NOT tid&159: 160 isn't pow2!)
        const int co  = t & 31;
        const int oyp = t >> 5;            // 0..4
        const float bias = s_b2[co];
        float acc0[10], acc1[10];
        #pragma unroll
        for (int i = 0; i < 10; i++) { acc0[i] = bias; acc1[i] = bias; }

        const float* p1base = s_p1 + im * 2304;

        #pragma unroll 1
        for (int ci = 0; ci < 16; ci++) {
            // 9 weights (HWIO, lanes=co consecutive -> conflict-free)
            const float* wbase = s_w2 + ci * 32 + co;
            float w[9];
            #pragma unroll
            for (int k = 0; k < 9; k++) w[k] = wbase[k * 512];

            // 4 activation rows serve both output rows; stream one row at a time
            const float* rb = p1base + (ci * 12 + 2 * oyp) * 12;
            #pragma unroll
            for (int r = 0; r < 4; r++) {
                const float4* rp = (const float4*)(rb + r * 12);
                const float4 A = rp[0], Bv = rp[1], C = rp[2];
                const float a[12] = {A.x, A.y, A.z, A.w, Bv.x, Bv.y, Bv.z, Bv.w,
                                     C.x, C.y, C.z, C.w};
                if (r < 3) {               // row r is tap-row r for output row 0
                    const float w0 = w[r * 3], w1 = w[r * 3 + 1], w2 = w[r * 3 + 2];
                    #pragma unroll
                    for (int ox = 0; ox < 10; ox++) {
                        acc0[ox] += a[ox] * w0;
                        acc0[ox] += a[ox + 1] * w1;
                        acc0[ox] += a[ox + 2] * w2;
                    }
                }
                if (r >= 1) {              // row r is tap-row r-1 for output row 1
                    const float w0 = w[(r - 1) * 3], w1 = w[(r - 1) * 3 + 1],
                                w2 = w[(r - 1) * 3 + 2];
                    #pragma unroll
                    for (int ox = 0; ox < 10; ox++) {
                        acc1[ox] += a[ox] * w0;
                        acc1[ox] += a[ox + 1] * w1;
                        acc1[ox] += a[ox + 2] * w2;
                    }
                }
            }
        }
        // fused relu + 2x2 pool: 5 pooled outputs, NHWC flatten [(oyp*5+c)*32+co]
        float* dst = s_p2 + im * 800 + (oyp * 5) * 32 + co;
        #pragma unroll
        for (int c = 0; c < 5; c++) {
            const float m = fmaxf(fmaxf(acc0[2 * c], acc0[2 * c + 1]),
                                  fmaxf(acc1[2 * c], acc1[2 * c + 1]));
            dst[c * 32] = fmaxf(m, 0.0f);
        }
    }
    __syncthreads();

    // ---------------- dense 800 -> 4, both images (one weight load serves both) ----
    {
        float pA0 = 0.f, pA1 = 0.f, pA2 = 0.f, pA3 = 0.f;
        float pB0 = 0.f, pB1 = 0.f, pB2 = 0.f, pB3 = 0.f;
        for (int k = tid; k < 800; k += 320) {
            const float vA = s_p2[k];
            const float vB = s_p2[800 + k];
            const float4 w = *(const float4*)(dwg + k * 4);
            pA0 += vA * w.x; pA1 += vA * w.y; pA2 += vA * w.z; pA3 += vA * w.w;
            pB0 += vB * w.x; pB1 += vB * w.y; pB2 += vB * w.z; pB3 += vB * w.w;
        }
        #pragma unroll
        for (int off = 16; off; off >>= 1) {
            pA0 += __shfl_down_sync(0xffffffffu, pA0, off);
            pA1 += __shfl_down_sync(0xffffffffu, pA1, off);
            pA2 += __shfl_down_sync(0xffffffffu, pA2, off);
            pA3 += __shfl_down_sync(0xffffffffu, pA3, off);
            pB0 += __shfl_down_sync(0xffffffffu, pB0, off);
            pB1 += __shfl_down_sync(0xffffffffu, pB1, off);
            pB2 += __shfl_down_sync(0xffffffffu, pB2, off);
            pB3 += __shfl_down_sync(0xffffffffu, pB3, off);
        }
        if ((tid & 31) == 0) {
            atomicAdd(&s_feat[0], pA0);
            atomicAdd(&s_feat[1], pA1);
            atomicAdd(&s_feat[2], pA2);
            atomicAdd(&s_feat[3], pA3);
            atomicAdd(&s_feat[4], pB0);
            atomicAdd(&s_feat[5], pB1);
            atomicAdd(&s_feat[6], pB2);
            atomicAdd(&s_feat[7], pB3);
        }
    }
    __syncthreads();

    // ---------------- analytic quantum circuit + sigmoid ---------------------------
    if (tid < 8) {
        const int im = tid >> 2;
        const int j  = tid & 3;
        if (im == 0 || has2) {
            float pr1[4];
            #pragma unroll
            for (int i = 0; i < 4; i++) {
                const float f = tanhf(s_feat[im * 4 + i]);
                pr1[i] = 0.5f * (1.0f + sinf(f));
            }
            float wj[4];
            #pragma unroll
            for (int i = 0; i < 4; i++) wj[i] = qwg[i * 4 + j];

            float q = 0.0f;
            #pragma unroll
            for (int b = 0; b < 16; b++) {
                float prob = 1.0f, ang = 0.0f;
                #pragma unroll
                for (int i = 0; i < 4; i++) {
                    if (b & (1 << i)) { prob *= pr1[i];        ang += wj[i]; }
                    else              { prob *= 1.0f - pr1[i]; }
                }
                q -= prob * sinf(ang);
            }
            out[(img0 + im) * 4 + j] = 1.0f / (1.0f + expf(-10.0f * q));
        }
    }
}

extern "C" void kernel_launch(void* const* d_in, const int* in_sizes, int n_in,
                              void* d_out, int out_size)
{
    const float* x   = (const float*)d_in[0];
    const float* w1  = (const float*)d_in[1];
    const float* b1  = (const float*)d_in[2];
    const float* w2  = (const float*)d_in[3];
    const float* b2  = (const float*)d_in[4];
    const float* dw  = (const float*)d_in[5];
    const float* db  = (const float*)d_in[6];
    const float* qw  = (const float*)d_in[7];
    float* out = (float*)d_out;

    const int B = in_sizes[0] / 784;   // NHWC 28*28*1
    static bool attr_set = false;
    if (!attr_set) {
        cudaFuncSetAttribute(hybrid_kernel,
                             cudaFuncAttributeMaxDynamicSharedMemorySize, SM_BYTES);
        attr_set = true;
    }
    hybrid_kernel<<<(B + 1) / 2, 320, SM_BYTES>>>(x, w1, b1, w2, b2, dw, db, qw, out, B);
}